// round 15
// baseline (speedup 1.0000x reference)
#include <cuda_runtime.h>
#include <cuda_fp16.h>
#include <math.h>
#include <stdint.h>

#define F_ 4
#define E_ 8
#define B_ 4096
#define D_ 512
#define H_ 1024
#define O_ 512
#define FE_ (F_*E_)

// GEMM tiling: BM=128, BN=256, BK=64. Warp tile 64x64 (2x4 warp grid).
#define BM 128
#define BN 256
#define BK 64
#define ATILE_B 16384                // 128 rows x 128B
#define BTILE_B 32768                // 256 rows x 128B
#define STAGE_B (ATILE_B + BTILE_B)  // 48KB
#define NSTG 3
#define SMEM_TOTAL (NSTG * STAGE_B + 1024)
#define KSPLIT 16

// ---------------------------------------------------------------------------
// Device scratch (no cudaMalloc allowed)
// ---------------------------------------------------------------------------
__device__ __align__(1024) float g_gate[F_ * B_ * E_];
__device__ __align__(1024) float g_bias[(size_t)B_ * O_];
__device__ __align__(1024) float g_part[(size_t)KSPLIT * B_ * O_];
__device__ __align__(1024) __half g_A[(size_t)F_ * B_ * D_];        // features fp16
__device__ __align__(1024) __half g_W1[(size_t)FE_ * H_ * D_];      // W1^T [fe][H][D]
__device__ __align__(1024) __half g_W2[(size_t)FE_ * O_ * H_];      // W2^T [fe][O][H]
__device__ __align__(1024) __half g_H[(size_t)FE_ * B_ * H_];       // gated hidden fp16

// ---------------------------------------------------------------------------
// PTX helpers (baseline ISA only — valid on plain sm_103 target)
// ---------------------------------------------------------------------------
__device__ __forceinline__ uint32_t smem_u32(const void* p) {
    return (uint32_t)__cvta_generic_to_shared(p);
}
__device__ __forceinline__ void cp16(uint32_t dst, const void* src) {
    asm volatile("cp.async.cg.shared.global [%0], [%1], 16;"
                 :: "r"(dst), "l"(__cvta_generic_to_global(src)) : "memory");
}
__device__ __forceinline__ void cp_commit() {
    asm volatile("cp.async.commit_group;" ::: "memory");
}
__device__ __forceinline__ void cp_wait1() {
    asm volatile("cp.async.wait_group 1;" ::: "memory");
}
__device__ __forceinline__ void ldsm4(uint32_t* r, uint32_t addr) {
    asm volatile("ldmatrix.sync.aligned.m8n8.x4.shared.b16 {%0,%1,%2,%3}, [%4];"
                 : "=r"(r[0]), "=r"(r[1]), "=r"(r[2]), "=r"(r[3]) : "r"(addr));
}
__device__ __forceinline__ void mma16816(float* c, const uint32_t* a, const uint32_t* b) {
    asm volatile(
        "mma.sync.aligned.m16n8k16.row.col.f32.f16.f16.f32 "
        "{%0,%1,%2,%3}, {%4,%5,%6,%7}, {%8,%9}, {%0,%1,%2,%3};"
        : "+f"(c[0]), "+f"(c[1]), "+f"(c[2]), "+f"(c[3])
        : "r"(a[0]), "r"(a[1]), "r"(a[2]), "r"(a[3]), "r"(b[0]), "r"(b[1]));
}

// Load one stage: A tile (128 rows) + B tile (256 rows), 128B SW128 rows.
__device__ __forceinline__ void load_stage(
    uint32_t base, const __half* A, const __half* Bt, int lda, int ldb, int tid)
{
#pragma unroll
    for (int i = 0; i < 4; ++i) {
        const int c   = tid + 256 * i;      // 0..1023
        const int row = c >> 3;
        const int col = c & 7;
        const uint32_t so = (uint32_t)(row * 128 + ((col * 16) ^ ((row & 7) << 4)));
        cp16(base + so, A + (size_t)row * lda + col * 8);
    }
#pragma unroll
    for (int i = 0; i < 8; ++i) {
        const int c   = tid + 256 * i;      // 0..2047
        const int row = c >> 3;
        const int col = c & 7;
        const uint32_t so = (uint32_t)(row * 128 + ((col * 16) ^ ((row & 7) << 4)));
        cp16(base + ATILE_B + so, Bt + (size_t)row * ldb + col * 8);
    }
    cp_commit();
}

// ============================================================================
// gate softmax (pre-scaled by 1/F). Warp-per-row, Wg staged in smem.
// ============================================================================
__global__ __launch_bounds__(256)
void gate_kernel(const float* __restrict__ feat,
                 const float* __restrict__ Wg,
                 const float* __restrict__ bg)
{
    __shared__ float wg_s[D_ * 9];
    const int tid = threadIdx.x;
    const int f = blockIdx.y;

    const float* wg = Wg + (size_t)f * D_ * E_;
#pragma unroll
    for (int i = 0; i < 16; ++i) {
        const int idx = tid + 256 * i;
        wg_s[(idx >> 3) * 9 + (idx & 7)] = wg[idx];
    }
    __syncthreads();

    const int wid = tid >> 5, lane = tid & 31;
    const int b = blockIdx.x * 8 + wid;
    const float* x = feat + ((size_t)f * B_ + b) * D_;

    float acc[E_] = {0.f, 0.f, 0.f, 0.f, 0.f, 0.f, 0.f, 0.f};
#pragma unroll
    for (int k = 0; k < D_ / 32; ++k) {
        const int d = lane + 32 * k;
        const float xv = x[d];
        const float* w = wg_s + d * 9;
#pragma unroll
        for (int e = 0; e < E_; ++e) acc[e] = fmaf(xv, w[e], acc[e]);
    }
#pragma unroll
    for (int e = 0; e < E_; ++e) {
#pragma unroll
        for (int off = 16; off > 0; off >>= 1)
            acc[e] += __shfl_down_sync(0xFFFFFFFFu, acc[e], off);
    }
    if (lane == 0) {
#pragma unroll
        for (int e = 0; e < E_; ++e) acc[e] += bg[f * E_ + e];
        float mx = acc[0];
#pragma unroll
        for (int e = 1; e < E_; ++e) mx = fmaxf(mx, acc[e]);
        float s = 0.f;
#pragma unroll
        for (int e = 0; e < E_; ++e) { acc[e] = expf(acc[e] - mx); s += acc[e]; }
        const float inv = 1.f / (s * (float)F_);
#pragma unroll
        for (int e = 0; e < E_; ++e)
            g_gate[((size_t)f * B_ + b) * E_ + e] = acc[e] * inv;
    }
}

// ============================================================================
// bias[b][o] = sum_fe gate(f,b,e)/F * b2[fe][o]
// ============================================================================
__global__ void bias_kernel(const float* __restrict__ b2)
{
    const int o = blockIdx.x * 256 + threadIdx.x;
    const int b = blockIdx.y;
    float acc = 0.f;
#pragma unroll
    for (int fe = 0; fe < FE_; ++fe)
        acc = fmaf(g_gate[((size_t)(fe >> 3) * B_ + b) * E_ + (fe & 7)],
                   b2[(size_t)fe * O_ + o], acc);
    g_bias[(size_t)b * O_ + o] = acc;
}

// ============================================================================
// features fp32 -> fp16. 8 elems/thread.
// ============================================================================
__global__ void convA_kernel(const float* __restrict__ src)
{
    const size_t i = ((size_t)blockIdx.x * 256 + threadIdx.x) * 8;
    float4 a = *(const float4*)(src + i);
    float4 b = *(const float4*)(src + i + 4);
    uint4 h;
    __half2 h0 = __floats2half2_rn(a.x, a.y);
    __half2 h1 = __floats2half2_rn(a.z, a.w);
    __half2 h2 = __floats2half2_rn(b.x, b.y);
    __half2 h3 = __floats2half2_rn(b.z, b.w);
    h.x = *reinterpret_cast<uint32_t*>(&h0);
    h.y = *reinterpret_cast<uint32_t*>(&h1);
    h.z = *reinterpret_cast<uint32_t*>(&h2);
    h.w = *reinterpret_cast<uint32_t*>(&h3);
    *(uint4*)(g_A + i) = h;
}

// ============================================================================
// transpose: in[z][R][C] fp32 -> out[z][C][R] fp16
// ============================================================================
__global__ void convT_kernel(const float* __restrict__ in, int which)
{
    __half* oh;
    int R, C;
    if (which == 0) { oh = g_W1; R = D_; C = H_; }
    else            { oh = g_W2; R = H_; C = O_; }

    __shared__ float t[32][33];
    const size_t zo = (size_t)blockIdx.z * R * C;
    const int x = blockIdx.x * 32 + threadIdx.x;
    const int y = blockIdx.y * 32;
#pragma unroll
    for (int i = 0; i < 32; i += 8)
        t[threadIdx.y + i][threadIdx.x] = in[zo + (size_t)(y + threadIdx.y + i) * C + x];
    __syncthreads();
    const int xo = blockIdx.y * 32 + threadIdx.x;
    const int yo = blockIdx.x * 32;
#pragma unroll
    for (int i = 0; i < 32; i += 8) {
        float v = t[threadIdx.x][threadIdx.y + i];
        oh[zo + (size_t)(yo + threadIdx.y + i) * R + xo] = __float2half_rn(v);
    }
}

// ---------------------------------------------------------------------------
// Mainloop compute: one BK=64 stage. Warp tile 64x64 (2x4 warp grid).
// Per ks: 4 B-ldsm4 + 4 A-ldsm4, 32 MMAs.
// ---------------------------------------------------------------------------
struct LdsmOffsets {
    uint32_t offA[4], xvA[4];
    uint32_t offB[4], xvB[4];
    uint32_t cbA, cbB;
};
__device__ __forceinline__ void make_offsets(LdsmOffsets& o, int wid, int lane) {
    const int wm = wid & 1, wn = wid >> 1;
    o.cbA = ((lane >> 4) & 1) * 16;
    o.cbB = ((lane >> 3) & 1) * 16;
#pragma unroll
    for (int mi = 0; mi < 4; ++mi) {
        int r = wm * 64 + mi * 16 + (lane & 7) + ((lane >> 3) & 1) * 8;
        o.offA[mi] = r * 128;
        o.xvA[mi]  = (r & 7) << 4;
    }
#pragma unroll
    for (int p = 0; p < 4; ++p) {
        int r = wn * 64 + p * 16 + (lane & 7) + ((lane >> 4) & 1) * 8;
        o.offB[p] = r * 128;
        o.xvB[p]  = (r & 7) << 4;
    }
}
__device__ __forceinline__ void compute_stage(uint32_t base, const LdsmOffsets& o,
                                              float c[4][8][4]) {
#pragma unroll
    for (int ks = 0; ks < 4; ++ks) {
        uint32_t bf[8][2];
#pragma unroll
        for (int p = 0; p < 4; ++p) {
            const uint32_t col = ((uint32_t)(ks * 32) + o.cbB) ^ o.xvB[p];
            uint32_t t4[4];
            ldsm4(t4, base + ATILE_B + o.offB[p] + col);
            bf[2*p][0] = t4[0];   bf[2*p][1] = t4[1];
            bf[2*p+1][0] = t4[2]; bf[2*p+1][1] = t4[3];
        }
#pragma unroll
        for (int mi = 0; mi < 4; ++mi) {
            uint32_t ah[4];
            const uint32_t col = (((uint32_t)(ks * 32)) + o.cbA) ^ o.xvA[mi];
            ldsm4(ah, base + o.offA[mi] + col);
#pragma unroll
            for (int ni = 0; ni < 8; ++ni) mma16816(c[mi][ni], ah, bf[ni]);
        }
    }
}

// ============================================================================
// GEMM1: H[fe] = fp16( gate/F * relu( X[f] @ W1[fe] + b1[fe] ) )
// Grid: (H/BN, B/BM, FE)
// ============================================================================
__global__ __launch_bounds__(256, 1)
void gemm1_kernel(const float* __restrict__ b1)
{
    extern __shared__ char sm[];
    const uint32_t stg0 = (smem_u32(sm) + 1023u) & ~1023u;
    const int tid = threadIdx.x;
    const int wid = tid >> 5, lane = tid & 31;
    const int fe = blockIdx.z, f = fe >> 3, e = fe & 7;
    const int m0 = blockIdx.y * BM, n0 = blockIdx.x * BN;

    const __half* A  = g_A  + ((size_t)f * B_ + m0) * D_;
    const __half* Bt = g_W1 + ((size_t)fe * H_ + n0) * D_;

    LdsmOffsets off;
    make_offsets(off, wid, lane);

    float c[4][8][4];
#pragma unroll
    for (int i = 0; i < 4; ++i)
#pragma unroll
        for (int j = 0; j < 8; ++j)
#pragma unroll
            for (int q = 0; q < 4; ++q) c[i][j][q] = 0.f;

    const int NT = D_ / BK;   // 8
    load_stage(stg0,           A,      Bt,      D_, D_, tid);
    load_stage(stg0 + STAGE_B, A + BK, Bt + BK, D_, D_, tid);

    for (int t = 0; t < NT; ++t) {
        cp_wait1();
        __syncthreads();
        if (t + 2 < NT) {
            const int k0 = (t + 2) * BK;
            load_stage(stg0 + ((t + 2) % NSTG) * STAGE_B, A + k0, Bt + k0, D_, D_, tid);
        } else {
            cp_commit();
        }
        compute_stage(stg0 + (t % NSTG) * STAGE_B, off, c);
    }

    // Epilogue: +b1, relu, *gate, fp16 store
    const int wm = wid & 1, wn = wid >> 1;
    const int rr = lane >> 2, cc = (lane & 3) * 2;
    const float* b1p = b1 + (size_t)fe * H_ + n0 + wn * 64;
#pragma unroll
    for (int mi = 0; mi < 4; ++mi) {
        const int m = m0 + wm * 64 + mi * 16 + rr;
        const float g0 = g_gate[((size_t)f * B_ + m) * E_ + e];
        const float g1 = g_gate[((size_t)f * B_ + m + 8) * E_ + e];
        __half* ph = g_H + ((size_t)fe * B_ + m) * H_ + n0 + wn * 64;
#pragma unroll
        for (int ni = 0; ni < 8; ++ni) {
            const int nc = (ni >> 1) * 16 + (ni & 1) * 8 + cc;
            const float ba = b1p[nc], bb = b1p[nc + 1];
            __half2 v0 = __floats2half2_rn(fmaxf(c[mi][ni][0] + ba, 0.f) * g0,
                                           fmaxf(c[mi][ni][1] + bb, 0.f) * g0);
            *(uint32_t*)(ph + nc) = *reinterpret_cast<uint32_t*>(&v0);
            __half2 v1 = __floats2half2_rn(fmaxf(c[mi][ni][2] + ba, 0.f) * g1,
                                           fmaxf(c[mi][ni][3] + bb, 0.f) * g1);
            *(uint32_t*)(ph + 8 * H_ + nc) = *reinterpret_cast<uint32_t*>(&v1);
        }
    }
}

// ============================================================================
// GEMM2 (split-K): part[s] = sum_{fe in split s} H[fe] @ W2^T[fe].
// Grid: (O/BN, B/BM, KSPLIT), 2 fe per split, NT=32.
// ============================================================================
__global__ __launch_bounds__(256, 1)
void gemm2_kernel()
{
    extern __shared__ char sm[];
    const uint32_t stg0 = (smem_u32(sm) + 1023u) & ~1023u;
    const int tid = threadIdx.x;
    const int wid = tid >> 5, lane = tid & 31;
    const int m0 = blockIdx.y * BM, n0 = blockIdx.x * BN;
    const int split = blockIdx.z;
    const int fe0 = split * (FE_ / KSPLIT);

    LdsmOffsets off;
    make_offsets(off, wid, lane);

    float c[4][8][4];
#pragma unroll
    for (int i = 0; i < 4; ++i)
#pragma unroll
        for (int j = 0; j < 8; ++j)
#pragma unroll
            for (int q = 0; q < 4; ++q) c[i][j][q] = 0.f;

    auto ld = [&](int s, uint32_t buf) {
        const int fe = fe0 + (s >> 4);          // 16 stages per fe (H/BK)
        const int k0 = (s & 15) * BK;
        load_stage(buf,
                   g_H  + ((size_t)fe * B_ + m0) * H_ + k0,
                   g_W2 + ((size_t)fe * O_ + n0) * H_ + k0,
                   H_, H_, tid);
    };

    ld(0, stg0);
    ld(1, stg0 + STAGE_B);

    const int NT = (FE_ / KSPLIT) * (H_ / BK);   // 32
    for (int t = 0; t < NT; ++t) {
        cp_wait1();
        __syncthreads();
        if (t + 2 < NT) ld(t + 2, stg0 + ((t + 2) % NSTG) * STAGE_B);
        else cp_commit();
        compute_stage(stg0 + (t % NSTG) * STAGE_B, off, c);
    }

    // Epilogue: store fp32 partials
    const int wm = wid & 1, wn = wid >> 1;
    const int rr = lane >> 2, cc = (lane & 3) * 2;
    float* part = g_part + (size_t)split * B_ * O_;
#pragma unroll
    for (int mi = 0; mi < 4; ++mi) {
        const int m = m0 + wm * 64 + mi * 16 + rr;
        float* op = part + (size_t)m * O_ + n0 + wn * 64;
#pragma unroll
        for (int ni = 0; ni < 8; ++ni) {
            const int nc = (ni >> 1) * 16 + (ni & 1) * 8 + cc;
            *(float2*)(op + nc) = make_float2(c[mi][ni][0], c[mi][ni][1]);
            *(float2*)(op + 8 * O_ + nc) = make_float2(c[mi][ni][2], c[mi][ni][3]);
        }
    }
}

// ============================================================================
// reduce: out = bias + sum_s part[s]
// ============================================================================
__global__ void reduce_kernel(float* __restrict__ out)
{
    const size_t i = ((size_t)blockIdx.x * 256 + threadIdx.x) * 4;
    float4 a = *(const float4*)(g_bias + i);
#pragma unroll
    for (int s = 0; s < KSPLIT; ++s) {
        float4 p = *(const float4*)(g_part + (size_t)s * B_ * O_ + i);
        a.x += p.x; a.y += p.y; a.z += p.z; a.w += p.w;
    }
    *(float4*)(out + i) = a;
}

// ============================================================================
extern "C" void kernel_launch(void* const* d_in, const int* in_sizes, int n_in,
                              void* d_out, int out_size)
{
    const float* feat = (const float*)d_in[0];
    const float* W1   = (const float*)d_in[1];
    const float* b1   = (const float*)d_in[2];
    const float* W2   = (const float*)d_in[3];
    const float* b2   = (const float*)d_in[4];
    const float* Wg   = (const float*)d_in[5];
    const float* bg   = (const float*)d_in[6];
    float* out = (float*)d_out;

    cudaFuncSetAttribute(gemm1_kernel, cudaFuncAttributeMaxDynamicSharedMemorySize, SMEM_TOTAL);
    cudaFuncSetAttribute(gemm2_kernel, cudaFuncAttributeMaxDynamicSharedMemorySize, SMEM_TOTAL);

    gate_kernel<<<dim3(B_ / 8, F_), 256>>>(feat, Wg, bg);
    bias_kernel<<<dim3(O_ / 256, B_), 256>>>(b2);
    convA_kernel<<<(F_ * B_ * D_) / (256 * 8), 256>>>(feat);
    convT_kernel<<<dim3(H_ / 32, D_ / 32, FE_), dim3(32, 8)>>>(W1, 0);
    convT_kernel<<<dim3(O_ / 32, H_ / 32, FE_), dim3(32, 8)>>>(W2, 1);
    gemm1_kernel<<<dim3(H_ / BN, B_ / BM, FE_), 256, SMEM_TOTAL>>>(b1);
    gemm2_kernel<<<dim3(O_ / BN, B_ / BM, KSPLIT), 256, SMEM_TOTAL>>>();
    reduce_kernel<<<(B_ * O_) / (256 * 4), 256>>>(out);
}

// round 16
// speedup vs baseline: 1.1826x; 1.1826x over previous
#include <cuda_runtime.h>
#include <cuda_fp16.h>
#include <math.h>
#include <stdint.h>

#define F_ 4
#define E_ 8
#define B_ 4096
#define D_ 512
#define H_ 1024
#define O_ 512
#define FE_ (F_*E_)

// GEMM tiling: BM=128, BN=128, BK=64. 128 threads, warp grid 2x2, warp tile 64x64.
#define BM 128
#define BN 128
#define BK 64
#define TILE_B 16384                 // 128 rows x 128B
#define STAGE_B (2 * TILE_B)         // A + B = 32KB
#define NSTG 3
#define SMEM_TOTAL (NSTG * STAGE_B + 1024)
#define KSPLIT 8
#define NTHREADS 128

// ---------------------------------------------------------------------------
// Device scratch (no cudaMalloc allowed)
// ---------------------------------------------------------------------------
__device__ __align__(1024) float g_gate[F_ * B_ * E_];
__device__ __align__(1024) float g_bias[(size_t)B_ * O_];
__device__ __align__(1024) float g_part[(size_t)KSPLIT * B_ * O_];
__device__ __align__(1024) __half g_A[(size_t)F_ * B_ * D_];        // features fp16
__device__ __align__(1024) __half g_W1[(size_t)FE_ * H_ * D_];      // W1^T [fe][H][D]
__device__ __align__(1024) __half g_W2[(size_t)FE_ * O_ * H_];      // W2^T [fe][O][H]
__device__ __align__(1024) __half g_H[(size_t)FE_ * B_ * H_];       // gated hidden fp16

// ---------------------------------------------------------------------------
// PTX helpers (baseline ISA only — valid on plain sm_103 target)
// ---------------------------------------------------------------------------
__device__ __forceinline__ uint32_t smem_u32(const void* p) {
    return (uint32_t)__cvta_generic_to_shared(p);
}
__device__ __forceinline__ void cp16(uint32_t dst, const void* src) {
    asm volatile("cp.async.cg.shared.global [%0], [%1], 16;"
                 :: "r"(dst), "l"(__cvta_generic_to_global(src)) : "memory");
}
__device__ __forceinline__ void cp_commit() {
    asm volatile("cp.async.commit_group;" ::: "memory");
}
__device__ __forceinline__ void cp_wait1() {
    asm volatile("cp.async.wait_group 1;" ::: "memory");
}
__device__ __forceinline__ void ldsm4(uint32_t* r, uint32_t addr) {
    asm volatile("ldmatrix.sync.aligned.m8n8.x4.shared.b16 {%0,%1,%2,%3}, [%4];"
                 : "=r"(r[0]), "=r"(r[1]), "=r"(r[2]), "=r"(r[3]) : "r"(addr));
}
__device__ __forceinline__ void mma16816(float* c, const uint32_t* a, const uint32_t* b) {
    asm volatile(
        "mma.sync.aligned.m16n8k16.row.col.f32.f16.f16.f32 "
        "{%0,%1,%2,%3}, {%4,%5,%6,%7}, {%8,%9}, {%0,%1,%2,%3};"
        : "+f"(c[0]), "+f"(c[1]), "+f"(c[2]), "+f"(c[3])
        : "r"(a[0]), "r"(a[1]), "r"(a[2]), "r"(a[3]), "r"(b[0]), "r"(b[1]));
}

// Load one stage: A tile + B tile, each 128 rows x 64 fp16 (128B SW128 rows).
// 128 threads: 8 cp16 per tile per thread.
__device__ __forceinline__ void load_stage(
    uint32_t base, const __half* A, const __half* Bt, int lda, int ldb, int tid)
{
#pragma unroll
    for (int i = 0; i < 8; ++i) {
        const int c   = tid + NTHREADS * i;   // 0..1023
        const int row = c >> 3;
        const int col = c & 7;
        const uint32_t so = (uint32_t)(row * 128 + ((col * 16) ^ ((row & 7) << 4)));
        cp16(base + so,          A  + (size_t)row * lda + col * 8);
        cp16(base + TILE_B + so, Bt + (size_t)row * ldb + col * 8);
    }
    cp_commit();
}

// ============================================================================
// gate softmax (pre-scaled by 1/F). Warp-per-row, Wg staged in smem.
// ============================================================================
__global__ __launch_bounds__(256)
void gate_kernel(const float* __restrict__ feat,
                 const float* __restrict__ Wg,
                 const float* __restrict__ bg)
{
    __shared__ float wg_s[D_ * 9];
    const int tid = threadIdx.x;
    const int f = blockIdx.y;

    const float* wg = Wg + (size_t)f * D_ * E_;
#pragma unroll
    for (int i = 0; i < 16; ++i) {
        const int idx = tid + 256 * i;
        wg_s[(idx >> 3) * 9 + (idx & 7)] = wg[idx];
    }
    __syncthreads();

    const int wid = tid >> 5, lane = tid & 31;
    const int b = blockIdx.x * 8 + wid;
    const float* x = feat + ((size_t)f * B_ + b) * D_;

    float acc[E_] = {0.f, 0.f, 0.f, 0.f, 0.f, 0.f, 0.f, 0.f};
#pragma unroll
    for (int k = 0; k < D_ / 32; ++k) {
        const int d = lane + 32 * k;
        const float xv = x[d];
        const float* w = wg_s + d * 9;
#pragma unroll
        for (int e = 0; e < E_; ++e) acc[e] = fmaf(xv, w[e], acc[e]);
    }
#pragma unroll
    for (int e = 0; e < E_; ++e) {
#pragma unroll
        for (int off = 16; off > 0; off >>= 1)
            acc[e] += __shfl_down_sync(0xFFFFFFFFu, acc[e], off);
    }
    if (lane == 0) {
#pragma unroll
        for (int e = 0; e < E_; ++e) acc[e] += bg[f * E_ + e];
        float mx = acc[0];
#pragma unroll
        for (int e = 1; e < E_; ++e) mx = fmaxf(mx, acc[e]);
        float s = 0.f;
#pragma unroll
        for (int e = 0; e < E_; ++e) { acc[e] = expf(acc[e] - mx); s += acc[e]; }
        const float inv = 1.f / (s * (float)F_);
#pragma unroll
        for (int e = 0; e < E_; ++e)
            g_gate[((size_t)f * B_ + b) * E_ + e] = acc[e] * inv;
    }
}

// ============================================================================
// bias[b][o] = sum_fe gate(f,b,e)/F * b2[fe][o]
// ============================================================================
__global__ void bias_kernel(const float* __restrict__ b2)
{
    const int o = blockIdx.x * 256 + threadIdx.x;
    const int b = blockIdx.y;
    float acc = 0.f;
#pragma unroll
    for (int fe = 0; fe < FE_; ++fe)
        acc = fmaf(g_gate[((size_t)(fe >> 3) * B_ + b) * E_ + (fe & 7)],
                   b2[(size_t)fe * O_ + o], acc);
    g_bias[(size_t)b * O_ + o] = acc;
}

// ============================================================================
// features fp32 -> fp16. 8 elems/thread.
// ============================================================================
__global__ void convA_kernel(const float* __restrict__ src)
{
    const size_t i = ((size_t)blockIdx.x * 256 + threadIdx.x) * 8;
    float4 a = *(const float4*)(src + i);
    float4 b = *(const float4*)(src + i + 4);
    uint4 h;
    __half2 h0 = __floats2half2_rn(a.x, a.y);
    __half2 h1 = __floats2half2_rn(a.z, a.w);
    __half2 h2 = __floats2half2_rn(b.x, b.y);
    __half2 h3 = __floats2half2_rn(b.z, b.w);
    h.x = *reinterpret_cast<uint32_t*>(&h0);
    h.y = *reinterpret_cast<uint32_t*>(&h1);
    h.z = *reinterpret_cast<uint32_t*>(&h2);
    h.w = *reinterpret_cast<uint32_t*>(&h3);
    *(uint4*)(g_A + i) = h;
}

// ============================================================================
// transpose: in[z][R][C] fp32 -> out[z][C][R] fp16
// ============================================================================
__global__ void convT_kernel(const float* __restrict__ in, int which)
{
    __half* oh;
    int R, C;
    if (which == 0) { oh = g_W1; R = D_; C = H_; }
    else            { oh = g_W2; R = H_; C = O_; }

    __shared__ float t[32][33];
    const size_t zo = (size_t)blockIdx.z * R * C;
    const int x = blockIdx.x * 32 + threadIdx.x;
    const int y = blockIdx.y * 32;
#pragma unroll
    for (int i = 0; i < 32; i += 8)
        t[threadIdx.y + i][threadIdx.x] = in[zo + (size_t)(y + threadIdx.y + i) * C + x];
    __syncthreads();
    const int xo = blockIdx.y * 32 + threadIdx.x;
    const int yo = blockIdx.x * 32;
#pragma unroll
    for (int i = 0; i < 32; i += 8) {
        float v = t[threadIdx.x][threadIdx.y + i];
        oh[zo + (size_t)(yo + threadIdx.y + i) * R + xo] = __float2half_rn(v);
    }
}

// ---------------------------------------------------------------------------
// Mainloop compute: one BK=64 stage. 4 warps in 2(m)x2(n), warp tile 64x64.
// Per ks per warp: 4 B-ldsm4 + 4 A-ldsm4, 32 MMAs.
// ---------------------------------------------------------------------------
struct LdsmOffsets {
    uint32_t offA[4], xvA[4];
    uint32_t offB[4], xvB[4];
    uint32_t cbA, cbB;
};
__device__ __forceinline__ void make_offsets(LdsmOffsets& o, int wid, int lane) {
    const int wm = wid & 1, wn = (wid >> 1) & 1;
    o.cbA = ((lane >> 4) & 1) * 16;
    o.cbB = ((lane >> 3) & 1) * 16;
#pragma unroll
    for (int mi = 0; mi < 4; ++mi) {
        int r = wm * 64 + mi * 16 + (lane & 7) + ((lane >> 3) & 1) * 8;
        o.offA[mi] = r * 128;
        o.xvA[mi]  = (r & 7) << 4;
    }
#pragma unroll
    for (int p = 0; p < 4; ++p) {
        int r = wn * 64 + p * 16 + (lane & 7) + ((lane >> 4) & 1) * 8;
        o.offB[p] = r * 128;
        o.xvB[p]  = (r & 7) << 4;
    }
}
__device__ __forceinline__ void compute_stage(uint32_t base, const LdsmOffsets& o,
                                              float c[4][8][4]) {
#pragma unroll
    for (int ks = 0; ks < 4; ++ks) {
        uint32_t bf[8][2];
#pragma unroll
        for (int p = 0; p < 4; ++p) {
            const uint32_t col = ((uint32_t)(ks * 32) + o.cbB) ^ o.xvB[p];
            uint32_t t4[4];
            ldsm4(t4, base + TILE_B + o.offB[p] + col);
            bf[2*p][0] = t4[0];   bf[2*p][1] = t4[1];
            bf[2*p+1][0] = t4[2]; bf[2*p+1][1] = t4[3];
        }
#pragma unroll
        for (int mi = 0; mi < 4; ++mi) {
            uint32_t ah[4];
            const uint32_t col = (((uint32_t)(ks * 32)) + o.cbA) ^ o.xvA[mi];
            ldsm4(ah, base + o.offA[mi] + col);
#pragma unroll
            for (int ni = 0; ni < 8; ++ni) mma16816(c[mi][ni], ah, bf[ni]);
        }
    }
}

// ============================================================================
// GEMM1: H[fe] = fp16( gate/F * relu( X[f] @ W1[fe] + b1[fe] ) )
// Grid: (H/BN, B/BM, FE), 128 threads.
// ============================================================================
__global__ __launch_bounds__(NTHREADS, 2)
void gemm1_kernel(const float* __restrict__ b1)
{
    extern __shared__ char sm[];
    const uint32_t stg0 = (smem_u32(sm) + 1023u) & ~1023u;
    const int tid = threadIdx.x;
    const int wid = tid >> 5, lane = tid & 31;
    const int fe = blockIdx.z, f = fe >> 3, e = fe & 7;
    const int m0 = blockIdx.y * BM, n0 = blockIdx.x * BN;

    const __half* A  = g_A  + ((size_t)f * B_ + m0) * D_;
    const __half* Bt = g_W1 + ((size_t)fe * H_ + n0) * D_;

    LdsmOffsets off;
    make_offsets(off, wid, lane);

    float c[4][8][4];
#pragma unroll
    for (int i = 0; i < 4; ++i)
#pragma unroll
        for (int j = 0; j < 8; ++j)
#pragma unroll
            for (int q = 0; q < 4; ++q) c[i][j][q] = 0.f;

    const int NT = D_ / BK;   // 8
    load_stage(stg0,           A,      Bt,      D_, D_, tid);
    load_stage(stg0 + STAGE_B, A + BK, Bt + BK, D_, D_, tid);

    for (int t = 0; t < NT; ++t) {
        cp_wait1();
        __syncthreads();
        if (t + 2 < NT) {
            const int k0 = (t + 2) * BK;
            load_stage(stg0 + ((t + 2) % NSTG) * STAGE_B, A + k0, Bt + k0, D_, D_, tid);
        } else {
            cp_commit();
        }
        compute_stage(stg0 + (t % NSTG) * STAGE_B, off, c);
    }

    // Epilogue: +b1, relu, *gate, fp16 store
    const int wm = wid & 1, wn = (wid >> 1) & 1;
    const int rr = lane >> 2, cc = (lane & 3) * 2;
    const float* b1p = b1 + (size_t)fe * H_ + n0 + wn * 64;
#pragma unroll
    for (int mi = 0; mi < 4; ++mi) {
        const int m = m0 + wm * 64 + mi * 16 + rr;
        const float g0 = g_gate[((size_t)f * B_ + m) * E_ + e];
        const float g1 = g_gate[((size_t)f * B_ + m + 8) * E_ + e];
        __half* ph = g_H + ((size_t)fe * B_ + m) * H_ + n0 + wn * 64;
#pragma unroll
        for (int ni = 0; ni < 8; ++ni) {
            const int nc = (ni >> 1) * 16 + (ni & 1) * 8 + cc;
            const float ba = b1p[nc], bb = b1p[nc + 1];
            __half2 v0 = __floats2half2_rn(fmaxf(c[mi][ni][0] + ba, 0.f) * g0,
                                           fmaxf(c[mi][ni][1] + bb, 0.f) * g0);
            *(uint32_t*)(ph + nc) = *reinterpret_cast<uint32_t*>(&v0);
            __half2 v1 = __floats2half2_rn(fmaxf(c[mi][ni][2] + ba, 0.f) * g1,
                                           fmaxf(c[mi][ni][3] + bb, 0.f) * g1);
            *(uint32_t*)(ph + 8 * H_ + nc) = *reinterpret_cast<uint32_t*>(&v1);
        }
    }
}

// ============================================================================
// GEMM2 (split-K): part[s] = sum_{fe in split s} H[fe] @ W2^T[fe].
// Grid: (O/BN, B/BM, KSPLIT), 128 threads, NT = 64.
// ============================================================================
__global__ __launch_bounds__(NTHREADS, 2)
void gemm2_kernel()
{
    extern __shared__ char sm[];
    const uint32_t stg0 = (smem_u32(sm) + 1023u) & ~1023u;
    const int tid = threadIdx.x;
    const int wid = tid >> 5, lane = tid & 31;
    const int m0 = blockIdx.y * BM, n0 = blockIdx.x * BN;
    const int split = blockIdx.z;
    const int fe0 = split * (FE_ / KSPLIT);

    LdsmOffsets off;
    make_offsets(off, wid, lane);

    float c[4][8][4];
#pragma unroll
    for (int i = 0; i < 4; ++i)
#pragma unroll
        for (int j = 0; j < 8; ++j)
#pragma unroll
            for (int q = 0; q < 4; ++q) c[i][j][q] = 0.f;

    auto ld = [&](int s, uint32_t buf) {
        const int fe = fe0 + (s >> 4);          // 16 stages per fe (H/BK)
        const int k0 = (s & 15) * BK;
        load_stage(buf,
                   g_H  + ((size_t)fe * B_ + m0) * H_ + k0,
                   g_W2 + ((size_t)fe * O_ + n0) * H_ + k0,
                   H_, H_, tid);
    };

    ld(0, stg0);
    ld(1, stg0 + STAGE_B);

    const int NT = (FE_ / KSPLIT) * (H_ / BK);   // 64
    for (int t = 0; t < NT; ++t) {
        cp_wait1();
        __syncthreads();
        if (t + 2 < NT) ld(t + 2, stg0 + ((t + 2) % NSTG) * STAGE_B);
        else cp_commit();
        compute_stage(stg0 + (t % NSTG) * STAGE_B, off, c);
    }

    // Epilogue: store fp32 partials
    const int wm = wid & 1, wn = (wid >> 1) & 1;
    const int rr = lane >> 2, cc = (lane & 3) * 2;
    float* part = g_part + (size_t)split * B_ * O_;
#pragma unroll
    for (int mi = 0; mi < 4; ++mi) {
        const int m = m0 + wm * 64 + mi * 16 + rr;
        float* op = part + (size_t)m * O_ + n0 + wn * 64;
#pragma unroll
        for (int ni = 0; ni < 8; ++ni) {
            const int nc = (ni >> 1) * 16 + (ni & 1) * 8 + cc;
            *(float2*)(op + nc) = make_float2(c[mi][ni][0], c[mi][ni][1]);
            *(float2*)(op + 8 * O_ + nc) = make_float2(c[mi][ni][2], c[mi][ni][3]);
        }
    }
}

// ============================================================================
// reduce: out = bias + sum_s part[s]
// ============================================================================
__global__ void reduce_kernel(float* __restrict__ out)
{
    const size_t i = ((size_t)blockIdx.x * 256 + threadIdx.x) * 4;
    float4 a = *(const float4*)(g_bias + i);
#pragma unroll
    for (int s = 0; s < KSPLIT; ++s) {
        float4 p = *(const float4*)(g_part + (size_t)s * B_ * O_ + i);
        a.x += p.x; a.y += p.y; a.z += p.z; a.w += p.w;
    }
    *(float4*)(out + i) = a;
}

// ============================================================================
extern "C" void kernel_launch(void* const* d_in, const int* in_sizes, int n_in,
                              void* d_out, int out_size)
{
    const float* feat = (const float*)d_in[0];
    const float* W1   = (const float*)d_in[1];
    const float* b1   = (const float*)d_in[2];
    const float* W2   = (const float*)d_in[3];
    const float* b2   = (const float*)d_in[4];
    const float* Wg   = (const float*)d_in[5];
    const float* bg   = (const float*)d_in[6];
    float* out = (float*)d_out;

    cudaFuncSetAttribute(gemm1_kernel, cudaFuncAttributeMaxDynamicSharedMemorySize, SMEM_TOTAL);
    cudaFuncSetAttribute(gemm2_kernel, cudaFuncAttributeMaxDynamicSharedMemorySize, SMEM_TOTAL);

    gate_kernel<<<dim3(B_ / 8, F_), 256>>>(feat, Wg, bg);
    bias_kernel<<<dim3(O_ / 256, B_), 256>>>(b2);
    convA_kernel<<<(F_ * B_ * D_) / (256 * 8), 256>>>(feat);
    convT_kernel<<<dim3(H_ / 32, D_ / 32, FE_), dim3(32, 8)>>>(W1, 0);
    convT_kernel<<<dim3(O_ / 32, H_ / 32, FE_), dim3(32, 8)>>>(W2, 1);
    gemm1_kernel<<<dim3(H_ / BN, B_ / BM, FE_), NTHREADS, SMEM_TOTAL>>>(b1);
    gemm2_kernel<<<dim3(O_ / BN, B_ / BM, KSPLIT), NTHREADS, SMEM_TOTAL>>>();
    reduce_kernel<<<(B_ * O_) / (256 * 4), 256>>>(out);
}